// round 1
// baseline (speedup 1.0000x reference)
#include <cuda_runtime.h>
#include <math.h>

#define NB   32
#define SL   20
#define DIM  256
#define BEAMW 4
#define EPSC 1e-8f
#define LNEPS 1e-5f

// ---------------- static device scratch (no allocations allowed) ----------------
__device__ float d_seq[NB * SL * DIM];                    // LN1(seq @ w_init + b)
__device__ float d_stacks[2][NB * BEAMW * SL * DIM];      // double-buffered beam stacks
__device__ int   d_p[2][NB * BEAMW];                      // top-of-stack pointer
__device__ int   d_q[2][NB * BEAMW];                      // consumed-token count
__device__ float d_cc[NB * BEAMW * 2 * DIM];              // [laster,last] rows (compose input)
__device__ float d_inter[NB * BEAMW * 4 * DIM];           // gelu(cc @ wcell1 + b)
__device__ float d_cont[NB * BEAMW * 4 * DIM];            // inter @ wcell2 + b
__device__ float d_red[NB * BEAMW * DIM];                 // reduce_items
__device__ float d_rs[NB * BEAMW];                        // reduce-branch log score
__device__ float d_ss[NB * BEAMW];                        // shift-branch log score
__device__ float d_bscore[NB * BEAMW];                    // per-beam score after selection

// ---------------- helpers ----------------
__device__ __forceinline__ float geluf(float x) {
    return 0.5f * x * (1.0f + erff(x * 0.7071067811865476f));
}
__device__ __forceinline__ float sigmoidf_(float x) {
    return 1.0f / (1.0f + expf(-x));
}

// 256-thread block reduce, result broadcast to all threads
__device__ __forceinline__ float blockReduceSum(float v, float* sbuf) {
    unsigned tid = threadIdx.x;
    #pragma unroll
    for (int o = 16; o > 0; o >>= 1) v += __shfl_down_sync(0xffffffffu, v, o);
    if ((tid & 31u) == 0u) sbuf[tid >> 5] = v;
    __syncthreads();
    if (tid == 0) {
        float r = 0.f;
        #pragma unroll
        for (int w = 0; w < 8; w++) r += sbuf[w];
        sbuf[0] = r;
    }
    __syncthreads();
    float r = sbuf[0];
    __syncthreads();
    return r;
}

// ---------------- kernel: seq = LN1(sequence @ w_init + b_init) ----------------
// 4 rows per block, 256 threads (one output column each)
__global__ void k_ln1(const float* __restrict__ sequence,
                      const float* __restrict__ w_init,
                      const float* __restrict__ b_init,
                      const float* __restrict__ g1,
                      const float* __restrict__ b1) {
    __shared__ float sX[4 * DIM];
    __shared__ float sred[8];
    int j = threadIdx.x;
    int row0 = blockIdx.x * 4;
    #pragma unroll
    for (int gi = 0; gi < 4; gi++)
        sX[gi * DIM + j] = sequence[(size_t)(row0 + gi) * DIM + j];
    __syncthreads();

    float acc[4] = {0.f, 0.f, 0.f, 0.f};
    for (int i = 0; i < DIM; i++) {
        float w = w_init[i * DIM + j];
        #pragma unroll
        for (int gi = 0; gi < 4; gi++) acc[gi] += sX[gi * DIM + i] * w;
    }
    float bb = b_init[j], gg = g1[j], bo = b1[j];
    #pragma unroll
    for (int gi = 0; gi < 4; gi++) {
        float y = acc[gi] + bb;
        float s1 = blockReduceSum(y, sred);
        float s2 = blockReduceSum(y * y, sred);
        float m = s1 * (1.0f / DIM);
        float var = s2 * (1.0f / DIM) - m * m;
        d_seq[(size_t)(row0 + gi) * DIM + j] = (y - m) * rsqrtf(var + LNEPS) * gg + bo;
    }
}

// ---------------- kernel: init beam 0 per batch item ----------------
__global__ void k_init(const float* __restrict__ input_mask) {
    int n = blockIdx.x;
    int j = threadIdx.x;
    float* stk = &d_stacks[0][(size_t)(n * BEAMW) * SL * DIM];
    stk[0 * DIM + j] = d_seq[(size_t)(n * SL + 0) * DIM + j];
    stk[1 * DIM + j] = d_seq[(size_t)(n * SL + 1) * DIM + j];
    if (j == 0) {
        d_p[0][n * BEAMW] = (input_mask[n * SL + 1] > 0.5f) ? 1 : 0;
        d_q[0][n * BEAMW] = 0;
    }
}

// ---------------- kernel: gather win, conv GEMM + gelu, scorer, rs/ss ----------------
// 4 (n,k) rows per block; 256 threads = one conv output column each
__global__ void k_conv_score(int A, int K,
                             const float* __restrict__ conv_w,
                             const float* __restrict__ conv_b,
                             const float* __restrict__ scorer_w,
                             const float* __restrict__ scorer_b,
                             const float* __restrict__ start,
                             const float* __restrict__ input_mask) {
    __shared__ float sW[4 * 3 * DIM];   // 4 rows x 768
    __shared__ float sred[8];
    __shared__ float sums[4];
    int j = threadIdx.x;
    int m0 = blockIdx.x * 4;

    for (int gi = 0; gi < 4; gi++) {
        int m = m0 + gi;
        int n = m / K, k = m % K;
        int p = d_p[A][n * BEAMW + k];
        int q = d_q[A][n * BEAMW + k];
        const float* stk = &d_stacks[A][(size_t)(n * BEAMW + k) * SL * DIM];
        float c1 = (p >= 1) ? stk[(p - 1) * DIM + j] : start[j];
        float c2 = stk[p * DIM + j];
        float cu = (q < SL - 2) ? d_seq[(size_t)(n * SL + 2 + q) * DIM + j] : 0.f;
        sW[gi * 768 + j]       = c1;
        sW[gi * 768 + 256 + j] = c2;
        sW[gi * 768 + 512 + j] = cu;
        d_cc[(size_t)m * 512 + j]       = c1;
        d_cc[(size_t)m * 512 + 256 + j] = c2;
    }
    __syncthreads();

    float a0 = 0.f, a1 = 0.f, a2 = 0.f, a3 = 0.f;
    for (int i = 0; i < 768; i++) {
        float w = conv_w[i * DIM + j];
        a0 += sW[i] * w;
        a1 += sW[768 + i] * w;
        a2 += sW[1536 + i] * w;
        a3 += sW[2304 + i] * w;
    }
    float bb = conv_b[j];
    float sw = scorer_w[j];
    float y[4];
    y[0] = geluf(a0 + bb); y[1] = geluf(a1 + bb);
    y[2] = geluf(a2 + bb); y[3] = geluf(a3 + bb);
    #pragma unroll
    for (int gi = 0; gi < 4; gi++)
        sums[gi] = blockReduceSum(y[gi] * sw, sred);

    if (j == 0) {
        float sb = scorer_b[0];
        for (int gi = 0; gi < 4; gi++) {
            int m = m0 + gi;
            int n = m / K, k = m % K;
            int p = d_p[A][n * BEAMW + k];
            int q = d_q[A][n * BEAMW + k];
            float dec = sigmoidf_(sums[gi] + sb);
            float lp  = (p >= 1) ? 1.0f : 0.0f;
            float cmf = (q < SL - 2) ? input_mask[n * SL + 2 + q] : 0.0f;
            float bz  = ((lp == 0.0f) && (cmf == 0.0f)) ? 1.0f : 0.0f;
            float rs = cmf * dec + (1.0f - cmf);
            rs = lp * rs;
            rs = bz + (1.0f - bz) * rs;
            rs = logf(rs + EPSC);
            float ss = lp * (1.0f - dec) + (1.0f - lp);
            ss = cmf * ss;
            ss = (1.0f - bz) * ss;
            ss = logf(ss + EPSC);
            d_rs[m] = rs;
            d_ss[m] = ss;
        }
    }
}

// ---------------- kernel: tiled fp32 GEMM, C = act(A@B + bias) ----------------
// block tile 32x32, 256 threads (16x16), 2x2 per thread
__global__ void k_gemm(const float* __restrict__ Am, const float* __restrict__ Bm,
                       const float* __restrict__ bias, float* __restrict__ Cm,
                       int M, int Ka, int Ncols, int act) {
    __shared__ float As[32][33];
    __shared__ float Bs[32][33];
    int t = threadIdx.x;
    int tx = t & 15, ty = t >> 4;
    int colBase = blockIdx.x * 32;
    int rowBase = blockIdx.y * 32;
    float c00 = 0.f, c01 = 0.f, c10 = 0.f, c11 = 0.f;

    for (int k0 = 0; k0 < Ka; k0 += 32) {
        #pragma unroll
        for (int e = 0; e < 4; e++) {
            int idx = t + e * 256;
            int r = idx >> 5, c = idx & 31;
            As[r][c] = Am[(size_t)(rowBase + r) * Ka + k0 + c];
            Bs[r][c] = Bm[(size_t)(k0 + r) * Ncols + colBase + c];
        }
        __syncthreads();
        #pragma unroll
        for (int kk = 0; kk < 32; kk++) {
            float av0 = As[ty * 2][kk], av1 = As[ty * 2 + 1][kk];
            float bv0 = Bs[kk][tx * 2], bv1 = Bs[kk][tx * 2 + 1];
            c00 += av0 * bv0; c01 += av0 * bv1;
            c10 += av1 * bv0; c11 += av1 * bv1;
        }
        __syncthreads();
    }
    int r0 = rowBase + ty * 2, c0 = colBase + tx * 2;
    float bb0 = bias[c0], bb1 = bias[c0 + 1];
    float o00 = c00 + bb0, o01 = c01 + bb1, o10 = c10 + bb0, o11 = c11 + bb1;
    if (act == 1) { o00 = geluf(o00); o01 = geluf(o01); o10 = geluf(o10); o11 = geluf(o11); }
    Cm[(size_t)r0 * Ncols + c0]           = o00;
    Cm[(size_t)r0 * Ncols + c0 + 1]       = o01;
    Cm[(size_t)(r0 + 1) * Ncols + c0]     = o10;
    Cm[(size_t)(r0 + 1) * Ncols + c0 + 1] = o11;
}

// ---------------- kernel: gates + LN2 -> reduce_items ----------------
__global__ void k_compose(const float* __restrict__ ln2_g, const float* __restrict__ ln2_b) {
    __shared__ float sred[8];
    int m = blockIdx.x;
    int j = threadIdx.x;
    const float* ct = &d_cont[(size_t)m * 1024];
    float g0 = sigmoidf_(ct[j]);
    float g1 = sigmoidf_(ct[256 + j]);
    float g2 = sigmoidf_(ct[512 + j]);
    float pr = ct[768 + j];
    float c1 = d_cc[(size_t)m * 512 + j];
    float c2 = d_cc[(size_t)m * 512 + 256 + j];
    float x = g0 * c1 + g1 * c2 + g2 * pr;
    float s1 = blockReduceSum(x, sred);
    float s2 = blockReduceSum(x * x, sred);
    float mn = s1 * (1.0f / DIM);
    float var = s2 * (1.0f / DIM) - mn * mn;
    d_red[(size_t)m * DIM + j] = (x - mn) * rsqrtf(var + LNEPS) * ln2_g[j] + ln2_b[j];
}

// ---------------- kernel: candidate scoring order / stable top-k / beam gather ----------------
__global__ void k_update(int A, int K, const float* __restrict__ input_mask) {
    int n = blockIdx.x;
    int tid = threadIdx.x;
    int B = A ^ 1;
    int C = 2 * K;
    int Knew = (C < BEAMW) ? C : BEAMW;
    __shared__ int sel[BEAMW];

    if (tid == 0) {
        float sc[2 * BEAMW];
        for (int c = 0; c < C; c++)
            sc[c] = (c < K) ? d_rs[n * K + c] : d_ss[n * K + (c - K)];
        if (C <= BEAMW) {
            // reference does NOT sort when 2K <= BEAM: keep concat order
            for (int s = 0; s < Knew; s++) { sel[s] = s; d_bscore[n * BEAMW + s] = sc[s]; }
        } else {
            bool used[2 * BEAMW];
            for (int c = 0; c < C; c++) used[c] = false;
            for (int s = 0; s < Knew; s++) {
                int best = -1; float bv = 0.f;
                for (int c = 0; c < C; c++) {
                    if (used[c]) continue;
                    if (best < 0 || sc[c] > bv) { best = c; bv = sc[c]; }  // strict >: stable ties
                }
                used[best] = true;
                sel[s] = best;
                d_bscore[n * BEAMW + s] = bv;
            }
        }
    }
    __syncthreads();

    for (int s = 0; s < Knew; s++) {
        int c = sel[s];
        bool isred = (c < K);
        int k = isred ? c : (c - K);
        int p = d_p[A][n * BEAMW + k];
        int q = d_q[A][n * BEAMW + k];
        int lp = (p >= 1) ? 1 : 0;
        float cmf = (q < SL - 2) ? input_mask[n * SL + 2 + q] : 0.0f;
        int cm = (cmf > 0.5f) ? 1 : 0;

        int wr_pos, newp, newq;
        const float* wr_src = 0;
        if (isred) {
            newq = q;
            if (lp) { wr_pos = p - 1; newp = p - 1; wr_src = &d_red[(size_t)(n * K + k) * DIM]; }
            else    { wr_pos = -1;    newp = p; }
        } else {
            newq = q + 1;
            if (cm) { wr_pos = p + 1; newp = p + 1; wr_src = &d_seq[(size_t)(n * SL + 2 + q) * DIM]; }
            else    { wr_pos = -1;    newp = p; }
        }
        const float* src = &d_stacks[A][(size_t)(n * BEAMW + k) * SL * DIM];
        float* dst       = &d_stacks[B][(size_t)(n * BEAMW + s) * SL * DIM];
        int len = (newp + 1) * DIM;   // entries above top are never read before rewrite
        for (int idx = tid; idx < len; idx += 256) {
            int pos = idx >> 8;
            float v = (pos == wr_pos) ? wr_src[idx & 255] : src[idx];
            dst[idx] = v;
        }
        if (tid == 0) {
            d_p[B][n * BEAMW + s] = newp;
            d_q[B][n * BEAMW + s] = newq;
        }
    }
}

// ---------------- kernel: softmax over beam scores, weighted top-of-stack sum ----------------
__global__ void k_final(int A, float* __restrict__ out) {
    int n = blockIdx.x;
    int j = threadIdx.x;
    float sc[BEAMW];
    float mx = -1e30f;
    #pragma unroll
    for (int k = 0; k < BEAMW; k++) { sc[k] = d_bscore[n * BEAMW + k]; mx = fmaxf(mx, sc[k]); }
    float e[BEAMW], sum = 0.f;
    #pragma unroll
    for (int k = 0; k < BEAMW; k++) { e[k] = expf(sc[k] - mx); sum += e[k]; }
    float o = 0.f;
    #pragma unroll
    for (int k = 0; k < BEAMW; k++) {
        int p = d_p[A][n * BEAMW + k];
        o += (e[k] / sum) * d_stacks[A][((size_t)(n * BEAMW + k) * SL + p) * DIM + j];
    }
    out[(size_t)n * DIM + j] = o;
}

// ---------------- host launcher ----------------
extern "C" void kernel_launch(void* const* d_in, const int* in_sizes, int n_in,
                              void* d_out, int out_size) {
    const float* sequence   = (const float*)d_in[0];
    const float* input_mask = (const float*)d_in[1];
    const float* w_init     = (const float*)d_in[2];
    const float* b_init     = (const float*)d_in[3];
    const float* ln1_g      = (const float*)d_in[4];
    const float* ln1_b      = (const float*)d_in[5];
    const float* scorer_w   = (const float*)d_in[6];
    const float* scorer_b   = (const float*)d_in[7];
    const float* conv_w     = (const float*)d_in[8];
    const float* conv_b     = (const float*)d_in[9];
    const float* start      = (const float*)d_in[10];
    const float* wcell1_w   = (const float*)d_in[11];
    const float* wcell1_b   = (const float*)d_in[12];
    const float* wcell2_w   = (const float*)d_in[13];
    const float* wcell2_b   = (const float*)d_in[14];
    const float* ln2_g      = (const float*)d_in[15];
    const float* ln2_b      = (const float*)d_in[16];
    float* out = (float*)d_out;

    // get device pointers to globals for GEMM args
    // (device symbols are directly addressable from kernels; for k_gemm we pass
    //  raw pointers obtained via cudaGetSymbolAddress — allowed, no allocation)
    static float *p_cc = nullptr, *p_inter = nullptr, *p_cont = nullptr;
    if (!p_cc) {
        cudaGetSymbolAddress((void**)&p_cc, d_cc);
        cudaGetSymbolAddress((void**)&p_inter, d_inter);
        cudaGetSymbolAddress((void**)&p_cont, d_cont);
    }

    k_ln1<<<(NB * SL) / 4, 256>>>(sequence, w_init, b_init, ln1_g, ln1_b);
    k_init<<<NB, 256>>>(input_mask);

    int K = 1, buf = 0;
    for (int t = 2; t <= 2 * SL - 2; ++t) {
        int M = NB * K;
        k_conv_score<<<M / 4, 256>>>(buf, K, conv_w, conv_b, scorer_w, scorer_b,
                                     start, input_mask);
        k_gemm<<<dim3(1024 / 32, M / 32), 256>>>(p_cc,    wcell1_w, wcell1_b, p_inter,
                                                 M, 512, 1024, 1);
        k_gemm<<<dim3(1024 / 32, M / 32), 256>>>(p_inter, wcell2_w, wcell2_b, p_cont,
                                                 M, 1024, 1024, 0);
        k_compose<<<M, 256>>>(ln2_g, ln2_b);
        k_update<<<NB, 256>>>(buf, K, input_mask);
        buf ^= 1;
        K = (2 * K < BEAMW) ? 2 * K : BEAMW;
    }
    k_final<<<NB, 256>>>(buf, out);
}

// round 2
// speedup vs baseline: 1.6168x; 1.6168x over previous
#include <cuda_runtime.h>
#include <math.h>

#define NB    32
#define SL    20
#define DIM   256
#define BEAMW 4
#define G     128          // persistent grid size (<= 148 SMs, all co-resident)
#define EPSC  1e-8f
#define LNEPS 1e-5f

// ---------------- static device scratch (no allocations allowed) ----------------
__device__ float d_seq[NB * SL * DIM];                 // LN1(seq @ w_init + b)
__device__ float d_stk[2][NB * BEAMW * SL * DIM];      // double-buffered beam stacks
__device__ int   d_p[2][NB * BEAMW];                   // top-of-stack pointer
__device__ int   d_q[2][NB * BEAMW];                   // consumed-token count
__device__ float d_win[128 * 768];                     // gathered [laster,last,cur]
__device__ float d_cc[128 * 512];                      // [laster,last] (compose input)
__device__ float d_cpart[4 * 128 * 256];               // conv K-split partial sums
__device__ float d_inter[128 * 1024];                  // gelu(cc @ wcell1 + b)
__device__ float d_cont[128 * 1024];                   // inter @ wcell2 + b
__device__ float d_bscore[NB * BEAMW];                 // per-beam score after selection
__device__ unsigned g_cnt = 0;                         // grid barrier state
__device__ unsigned g_gen = 0;

// ---------------- grid barrier (sense-reversing, all G blocks resident) ----------------
__device__ __forceinline__ void gbar() {
    __syncthreads();
    if (threadIdx.x == 0) {
        volatile unsigned* gen = &g_gen;
        unsigned my = *gen;
        __threadfence();
        if (atomicAdd(&g_cnt, 1u) == (unsigned)(G - 1)) {
            g_cnt = 0;
            __threadfence();
            *gen = my + 1u;
        } else {
            while (*gen == my) { __nanosleep(32); }
        }
        __threadfence();
    }
    __syncthreads();
}

// ---------------- helpers ----------------
__device__ __forceinline__ float geluf(float x) {
    return 0.5f * x * (1.0f + erff(x * 0.7071067811865476f));
}
__device__ __forceinline__ float sigmoidf_(float x) {
    return 1.0f / (1.0f + expf(-x));
}

__device__ __forceinline__ float blockReduceSum(float v, float* sbuf) {
    unsigned tid = threadIdx.x;
    #pragma unroll
    for (int o = 16; o > 0; o >>= 1) v += __shfl_down_sync(0xffffffffu, v, o);
    if ((tid & 31u) == 0u) sbuf[tid >> 5] = v;
    __syncthreads();
    if (tid == 0) {
        float r = 0.f;
        #pragma unroll
        for (int w = 0; w < 8; w++) r += sbuf[w];
        sbuf[0] = r;
    }
    __syncthreads();
    float r = sbuf[0];
    __syncthreads();
    return r;
}

// ---------------- packed f32x2 primitives (FFMA2; only reachable via PTX) ----------------
__device__ __forceinline__ unsigned long long pack2(float lo, float hi) {
    unsigned long long r;
    asm("mov.b64 %0, {%1, %2};" : "=l"(r) : "f"(lo), "f"(hi));
    return r;
}
__device__ __forceinline__ void fma2(unsigned long long& d, unsigned long long a,
                                     unsigned long long b) {
    asm("fma.rn.f32x2 %0, %1, %2, %0;" : "+l"(d) : "l"(a), "l"(b));
}
__device__ __forceinline__ void unpack2(unsigned long long v, float& lo, float& hi) {
    asm("mov.b64 {%0, %1}, %2;" : "=f"(lo), "=f"(hi) : "l"(v));
}

// ---------------- 32x32 output tile GEMM, K consumed in 64-chunks ----------------
// thread = 1 row (lane) x 4 cols (warp*4..+3) as two f32x2 accumulators.
// A row-major [*, lda] at row0; B row-major [K, ldb] at col0; C at [row0][col0].
__device__ void gemm_tile32(const float* __restrict__ A, int lda,
                            const float* __restrict__ B, int ldb,
                            int k0, int nChunks,
                            float* __restrict__ C, int ldc,
                            const float* __restrict__ bias, int act,
                            float* sA, float* sB) {
    int tid  = threadIdx.x;
    int lane = tid & 31, warp = tid >> 5;
    unsigned long long acc01 = 0ull, acc23 = 0ull;
    int akk = tid & 63, ar = tid >> 6;   // A: col k0+akk, rows ar+4e
    int bc  = tid & 31, bk = tid >> 5;   // B: col bc, rows k0+bk+8e
    float ra[8], rb[8];
    #pragma unroll
    for (int e = 0; e < 8; e++) ra[e] = A[(size_t)(ar + 4 * e) * lda + k0 + akk];
    #pragma unroll
    for (int e = 0; e < 8; e++) rb[e] = B[(size_t)(k0 + bk + 8 * e) * ldb + bc];

    for (int ch = 0; ch < nChunks; ch++) {
        #pragma unroll
        for (int e = 0; e < 8; e++) sA[akk * 33 + ar + 4 * e] = ra[e];
        #pragma unroll
        for (int e = 0; e < 8; e++) sB[(bk + 8 * e) * 32 + bc] = rb[e];
        __syncthreads();
        if (ch + 1 < nChunks) {
            int kn = k0 + (ch + 1) * 64;
            #pragma unroll
            for (int e = 0; e < 8; e++) ra[e] = A[(size_t)(ar + 4 * e) * lda + kn + akk];
            #pragma unroll
            for (int e = 0; e < 8; e++) rb[e] = B[(size_t)(kn + bk + 8 * e) * ldb + bc];
        }
        #pragma unroll
        for (int kk = 0; kk < 64; kk++) {
            float a = sA[kk * 33 + lane];
            ulonglong2 b2 = *(const ulonglong2*)(sB + kk * 32 + warp * 4);
            unsigned long long ad = pack2(a, a);
            fma2(acc01, ad, b2.x);
            fma2(acc23, ad, b2.y);
        }
        __syncthreads();
    }
    float o0, o1, o2, o3;
    unpack2(acc01, o0, o1);
    unpack2(acc23, o2, o3);
    if (bias) {
        o0 += bias[warp * 4];     o1 += bias[warp * 4 + 1];
        o2 += bias[warp * 4 + 2]; o3 += bias[warp * 4 + 3];
    }
    if (act) { o0 = geluf(o0); o1 = geluf(o1); o2 = geluf(o2); o3 = geluf(o3); }
    float4 ov = make_float4(o0, o1, o2, o3);
    *(float4*)(C + (size_t)lane * ldc + warp * 4) = ov;
}

// ---------------- the persistent mega kernel ----------------
__global__ void __launch_bounds__(256, 1)
mega(const float* __restrict__ sequence, const float* __restrict__ input_mask,
     const float* __restrict__ w_init, const float* __restrict__ b_init,
     const float* __restrict__ ln1_g, const float* __restrict__ ln1_b,
     const float* __restrict__ scorer_w, const float* __restrict__ scorer_b,
     const float* __restrict__ conv_w, const float* __restrict__ conv_b,
     const float* __restrict__ start,
     const float* __restrict__ wcell1_w, const float* __restrict__ wcell1_b,
     const float* __restrict__ wcell2_w, const float* __restrict__ wcell2_b,
     const float* __restrict__ ln2_g, const float* __restrict__ ln2_b,
     float* __restrict__ out) {
    __shared__ __align__(16) float sA[64 * 33];  // also reused as sX (ln1) / red (EF)
    __shared__ __align__(16) float sB[64 * 32];
    __shared__ float sred[8];
    __shared__ float sscore[8];
    __shared__ int   ssel[BEAMW];

    int tid = threadIdx.x;
    int bid = blockIdx.x;

    // ---- init phase 1: seq = LN1(sequence @ w_init + b_init), 4 rows/job ----
    for (int job = bid; job < (NB * SL) / 4; job += G) {
        int row0 = job * 4;
        #pragma unroll
        for (int gi = 0; gi < 4; gi++)
            sA[gi * DIM + tid] = sequence[(size_t)(row0 + gi) * DIM + tid];
        __syncthreads();
        float acc[4] = {0.f, 0.f, 0.f, 0.f};
        for (int i = 0; i < DIM; i++) {
            float w = w_init[i * DIM + tid];
            #pragma unroll
            for (int gi = 0; gi < 4; gi++) acc[gi] += sA[gi * DIM + i] * w;
        }
        float bb = b_init[tid], gg = ln1_g[tid], bo = ln1_b[tid];
        #pragma unroll
        for (int gi = 0; gi < 4; gi++) {
            float y = acc[gi] + bb;
            float s1 = blockReduceSum(y, sred);
            float s2 = blockReduceSum(y * y, sred);
            float m = s1 * (1.0f / DIM);
            float var = s2 * (1.0f / DIM) - m * m;
            d_seq[(size_t)(row0 + gi) * DIM + tid] = (y - m) * rsqrtf(var + LNEPS) * gg + bo;
        }
        __syncthreads();
    }
    gbar();

    // ---- init phase 2: stacks init + first gather (K=1) ----
    if (bid < NB) {
        int n = bid;
        float* stk0 = d_stk[0] + (size_t)(n * BEAMW) * SL * DIM;
        stk0[tid]       = d_seq[(size_t)(n * SL + 0) * DIM + tid];
        stk0[DIM + tid] = d_seq[(size_t)(n * SL + 1) * DIM + tid];
        if (tid == 0) {
            d_p[0][n * BEAMW] = (input_mask[n * SL + 1] > 0.5f) ? 1 : 0;
            d_q[0][n * BEAMW] = 0;
        }
        __syncthreads();
        int p = d_p[0][n * BEAMW];
        float c1 = (p >= 1) ? stk0[(p - 1) * DIM + tid] : start[tid];
        float c2 = stk0[p * DIM + tid];
        float cu = d_seq[(size_t)(n * SL + 2) * DIM + tid];   // q = 0
        d_win[n * 768 + tid]       = c1;
        d_win[n * 768 + 256 + tid] = c2;
        d_win[n * 768 + 512 + tid] = cu;
        d_cc[n * 512 + tid]        = c1;
        d_cc[n * 512 + 256 + tid]  = c2;
    }
    gbar();

    int K = 1, buf = 0;
    for (int t = 2; t <= 2 * SL - 2; t++) {
        int M  = NB * K;
        int rt = M / 32;
        int newK = (2 * K < BEAMW) ? 2 * K : BEAMW;

        // ---- phase B: conv K-split partial tiles + cell1 tiles ----
        int convJobs = rt * 8 * 4;    // (row tiles) x (8 col tiles) x (4 K-splits)
        int c1Jobs   = rt * 32;       // (row tiles) x (32 col tiles)
        for (int job = bid; job < convJobs + c1Jobs; job += G) {
            if (job < convJobs) {
                int ks = job & 3;
                int r  = job >> 2;
                int ct = r & 7;
                int ri = r >> 3;
                gemm_tile32(d_win + (size_t)ri * 32 * 768, 768,
                            conv_w + ct * 32, 256,
                            ks * 192, 3,
                            d_cpart + ks * (128 * 256) + (size_t)ri * 32 * 256 + ct * 32, 256,
                            nullptr, 0, sA, sB);
            } else {
                int j2 = job - convJobs;
                int ct = j2 & 31;
                int ri = j2 >> 5;
                gemm_tile32(d_cc + (size_t)ri * 32 * 512, 512,
                            wcell1_w + ct * 32, 1024,
                            0, 8,
                            d_inter + (size_t)ri * 32 * 1024 + ct * 32, 1024,
                            wcell1_b + ct * 32, 1, sA, sB);
            }
        }
        gbar();

        // ---- phase C: cell2 tiles ----
        for (int job = bid; job < rt * 32; job += G) {
            int ct = job & 31;
            int ri = job >> 5;
            gemm_tile32(d_inter + (size_t)ri * 32 * 1024, 1024,
                        wcell2_w + ct * 32, 1024,
                        0, 16,
                        d_cont + (size_t)ri * 32 * 1024 + ct * 32, 1024,
                        wcell2_b + ct * 32, 0, sA, sB);
        }
        gbar();

        // ---- phase EF: score finalize + compose + top-k + beam copy + next gather ----
        if (bid < NB) {
            int n = bid;
            float* red = sA;   // [K][256]

            // 1. finalize scores
            for (int k = 0; k < K; k++) {
                int m = n * K + k;
                float s = d_cpart[m * 256 + tid]
                        + d_cpart[32768 + m * 256 + tid]
                        + d_cpart[65536 + m * 256 + tid]
                        + d_cpart[98304 + m * 256 + tid];
                float y = geluf(s + conv_b[tid]) * scorer_w[tid];
                float dot = blockReduceSum(y, sred);
                if (tid == 0) {
                    float dec = sigmoidf_(dot + scorer_b[0]);
                    int p = d_p[buf][n * BEAMW + k];
                    int q = d_q[buf][n * BEAMW + k];
                    float lp  = (p >= 1) ? 1.0f : 0.0f;
                    float cmf = (q < SL - 2) ? input_mask[n * SL + 2 + q] : 0.0f;
                    float bz  = ((lp == 0.0f) && (cmf == 0.0f)) ? 1.0f : 0.0f;
                    float rs = cmf * dec + (1.0f - cmf);
                    rs = lp * rs;
                    rs = bz + (1.0f - bz) * rs;
                    rs = logf(rs + EPSC);
                    float ss = lp * (1.0f - dec) + (1.0f - lp);
                    ss = cmf * ss;
                    ss = (1.0f - bz) * ss;
                    ss = logf(ss + EPSC);
                    sscore[k] = rs;
                    sscore[4 + k] = ss;
                }
            }
            // 2. compose (gates + LN2)
            for (int k = 0; k < K; k++) {
                int m = n * K + k;
                const float* cp = d_cont + (size_t)m * 1024;
                float x = sigmoidf_(cp[tid])       * d_cc[m * 512 + tid]
                        + sigmoidf_(cp[256 + tid]) * d_cc[m * 512 + 256 + tid]
                        + sigmoidf_(cp[512 + tid]) * cp[768 + tid];
                float s1 = blockReduceSum(x, sred);
                float s2 = blockReduceSum(x * x, sred);
                float mn = s1 * (1.0f / DIM);
                float var = s2 * (1.0f / DIM) - mn * mn;
                red[k * 256 + tid] = (x - mn) * rsqrtf(var + LNEPS) * ln2_g[tid] + ln2_b[tid];
            }
            // 3. stable top-k (concat order preserved when 2K <= BEAM)
            if (tid == 0) {
                int C = 2 * K;
                float sc[8];
                for (int c = 0; c < C; c++)
                    sc[c] = (c < K) ? sscore[c] : sscore[4 + (c - K)];
                if (C <= BEAMW) {
                    for (int s = 0; s < C; s++) { ssel[s] = s; d_bscore[n * BEAMW + s] = sc[s]; }
                } else {
                    bool used[8];
                    for (int c = 0; c < C; c++) used[c] = false;
                    for (int s = 0; s < BEAMW; s++) {
                        int best = -1; float bv = 0.f;
                        for (int c = 0; c < C; c++) {
                            if (used[c]) continue;
                            if (best < 0 || sc[c] > bv) { best = c; bv = sc[c]; }
                        }
                        used[best] = true;
                        ssel[s] = best;
                        d_bscore[n * BEAMW + s] = bv;
                    }
                }
            }
            __syncthreads();
            // 4. beam copy (prefix only; entries above top never read before rewrite)
            int nb2 = buf ^ 1;
            for (int s = 0; s < newK; s++) {
                int c = ssel[s];
                int isred = (c < K);
                int k = isred ? c : (c - K);
                int p = d_p[buf][n * BEAMW + k];
                int q = d_q[buf][n * BEAMW + k];
                int lp = (p >= 1);
                float cmf = (q < SL - 2) ? input_mask[n * SL + 2 + q] : 0.0f;
                int cm = (cmf > 0.5f);
                int wr_pos = -1, newp = p, newq = q;
                const float* wr_g = nullptr;
                int wr_sm = 0;
                if (isred) {
                    if (lp) { wr_pos = p - 1; newp = p - 1; wr_sm = 1; }
                } else {
                    newq = q + 1;
                    if (cm) { wr_pos = p + 1; newp = p + 1; wr_g = &d_seq[(size_t)(n * SL + 2 + q) * DIM]; }
                }
                const float* src = d_stk[buf] + (size_t)(n * BEAMW + k) * SL * DIM;
                float* dst       = d_stk[nb2] + (size_t)(n * BEAMW + s) * SL * DIM;
                int len = (newp + 1) * DIM;
                for (int idx = tid; idx < len; idx += 256) {
                    int pos = idx >> 8;
                    float v = (pos == wr_pos) ? (wr_sm ? red[k * 256 + (idx & 255)]
                                                       : wr_g[idx & 255])
                                              : src[idx];
                    dst[idx] = v;
                }
                if (tid == 0) {
                    d_p[nb2][n * BEAMW + s] = newp;
                    d_q[nb2][n * BEAMW + s] = newq;
                }
            }
            __syncthreads();
            // 5. gather for next iteration (this block owns batch n's new stacks)
            for (int s = 0; s < newK; s++) {
                int m2 = n * newK + s;
                int p = d_p[nb2][n * BEAMW + s];
                int q = d_q[nb2][n * BEAMW + s];
                const float* stk = d_stk[nb2] + (size_t)(n * BEAMW + s) * SL * DIM;
                float c1 = (p >= 1) ? stk[(p - 1) * DIM + tid] : start[tid];
                float c2 = stk[p * DIM + tid];
                float cu = (q < SL - 2) ? d_seq[(size_t)(n * SL + 2 + q) * DIM + tid] : 0.f;
                d_win[m2 * 768 + tid]       = c1;
                d_win[m2 * 768 + 256 + tid] = c2;
                d_win[m2 * 768 + 512 + tid] = cu;
                d_cc[m2 * 512 + tid]        = c1;
                d_cc[m2 * 512 + 256 + tid]  = c2;
            }
        }
        gbar();
        buf ^= 1;
        K = newK;
    }

    // ---- final: softmax over beam scores, weighted top-of-stack sum ----
    if (bid < NB) {
        int n = bid;
        float sc[BEAMW];
        float mx = -1e30f;
        #pragma unroll
        for (int k = 0; k < BEAMW; k++) {
            sc[k] = d_bscore[n * BEAMW + k];
            mx = fmaxf(mx, sc[k]);
        }
        float e[BEAMW], sum = 0.f;
        #pragma unroll
        for (int k = 0; k < BEAMW; k++) { e[k] = expf(sc[k] - mx); sum += e[k]; }
        float o = 0.f;
        #pragma unroll
        for (int k = 0; k < BEAMW; k++) {
            int p = d_p[buf][n * BEAMW + k];
            o += (e[k] / sum) * d_stk[buf][((size_t)(n * BEAMW + k) * SL + p) * DIM + tid];
        }
        out[(size_t)n * DIM + tid] = o;
    }
}

// ---------------- host launcher ----------------
extern "C" void kernel_launch(void* const* d_in, const int* in_sizes, int n_in,
                              void* d_out, int out_size) {
    const float* sequence   = (const float*)d_in[0];
    const float* input_mask = (const float*)d_in[1];
    const float* w_init     = (const float*)d_in[2];
    const float* b_init     = (const float*)d_in[3];
    const float* ln1_g      = (const float*)d_in[4];
    const float* ln1_b      = (const float*)d_in[5];
    const float* scorer_w   = (const float*)d_in[6];
    const float* scorer_b   = (const float*)d_in[7];
    const float* conv_w     = (const float*)d_in[8];
    const float* conv_b     = (const float*)d_in[9];
    const float* start      = (const float*)d_in[10];
    const float* wcell1_w   = (const float*)d_in[11];
    const float* wcell1_b   = (const float*)d_in[12];
    const float* wcell2_w   = (const float*)d_in[13];
    const float* wcell2_b   = (const float*)d_in[14];
    const float* ln2_g      = (const float*)d_in[15];
    const float* ln2_b      = (const float*)d_in[16];
    float* out = (float*)d_out;

    mega<<<G, 256>>>(sequence, input_mask, w_init, b_init, ln1_g, ln1_b,
                     scorer_w, scorer_b, conv_w, conv_b, start,
                     wcell1_w, wcell1_b, wcell2_w, wcell2_b, ln2_g, ln2_b, out);
}

// round 3
// speedup vs baseline: 1.8456x; 1.1415x over previous
#include <cuda_runtime.h>
#include <math.h>

#define NB    32
#define SL    20
#define DIM   256
#define BEAMW 4
#define G     128          // persistent grid (1 block/SM, all co-resident)
#define NT    512          // threads per block (2 teams of 256)
#define EPSC  1e-8f
#define LNEPS 1e-5f

// dynamic smem layout: per team: sA2 (64*33 f32x2 = 16896B) + sB (64*64 f32 = 16384B)
#define TEAM_BYTES 33280
#define SA2_WORDS  (64 * 33 * 2)
#define SMEM_DYN   (2 * TEAM_BYTES)

// ---------------- static device scratch ----------------
__device__ float d_seq[NB * SL * DIM];
__device__ float d_stk[2][NB * BEAMW * SL * DIM];
__device__ int   d_p[2][NB * BEAMW];
__device__ int   d_q[2][NB * BEAMW];
__device__ float d_win[128 * 768];
__device__ float d_cc[128 * 512];
__device__ float d_cpart[2 * 128 * 256];     // conv partials (ks2)
__device__ float d_inter[128 * 1024];        // gelu(cc @ wcell1 + b)
__device__ float d_c2[2 * 128 * 1024];       // cell2 partials (ks2)
__device__ float d_bscore[NB * BEAMW];
__device__ unsigned g_cnt = 0;
__device__ unsigned g_gen = 0;

// ---------------- grid barrier ----------------
__device__ __forceinline__ void gbar() {
    __syncthreads();
    if (threadIdx.x == 0) {
        volatile unsigned* gen = &g_gen;
        unsigned my = *gen;
        __threadfence();
        if (atomicAdd(&g_cnt, 1u) == (unsigned)(G - 1)) {
            g_cnt = 0;
            __threadfence();
            *gen = my + 1u;
        } else {
            while (*gen == my) { __nanosleep(32); }
        }
        __threadfence();
    }
    __syncthreads();
}

// ---------------- helpers ----------------
__device__ __forceinline__ float geluf(float x) {
    return 0.5f * x * (1.0f + erff(x * 0.7071067811865476f));
}
__device__ __forceinline__ float sigmoidf_(float x) {
    return 1.0f / (1.0f + expf(-x));
}

// 512-thread block: two independent 256-thread halves; returns the half-sum
__device__ __forceinline__ float halfReduceSum(float v, float* sbuf) {
    int tid = threadIdx.x;
    #pragma unroll
    for (int o = 16; o > 0; o >>= 1) v += __shfl_down_sync(0xffffffffu, v, o);
    if ((tid & 31) == 0) sbuf[tid >> 5] = v;
    __syncthreads();
    int h = tid >> 8;
    float r = 0.f;
    #pragma unroll
    for (int w = 0; w < 8; w++) r += sbuf[h * 8 + w];
    __syncthreads();
    return r;
}

// ---------------- packed f32x2 FFMA ----------------
__device__ __forceinline__ void fma2(unsigned long long& d, unsigned long long a,
                                     unsigned long long b) {
    asm("fma.rn.f32x2 %0, %1, %2, %0;" : "+l"(d) : "l"(a), "l"(b));
}
__device__ __forceinline__ void unpack2(unsigned long long v, float& lo, float& hi) {
    asm("mov.b64 {%0, %1}, %2;" : "=f"(lo), "=f"(hi) : "l"(v));
}

// ---------------- 32 rows x 64 cols tile GEMM, K split across 2 teams ----------------
// thread = 1 row (lane) x 8 cols (twarp*8). nch = chunks of 64 K per team.
__device__ void gemm_tile(const float* __restrict__ A, int lda,
                          const float* __restrict__ Bw, int ldb,
                          int k0, int nch,
                          float* __restrict__ C, int ldc,
                          const float* __restrict__ bias, int act,
                          char* dsm) {
    int tid  = threadIdx.x;
    int team = tid >> 8;
    int ttid = tid & 255;
    int lane = ttid & 31, tw = ttid >> 5;
    float* sA2 = (float*)(dsm + team * TEAM_BYTES);
    float* sB  = (float*)(dsm + team * TEAM_BYTES + 16896);

    int kbase = k0 + team * nch * 64;
    unsigned long long acc0 = 0ull, acc1 = 0ull, acc2 = 0ull, acc3 = 0ull;

    // register staging indices
    int aIdx0 = ttid, r0 = aIdx0 >> 4, ac0 = aIdx0 & 15;
    int aIdx1 = ttid + 256, r1 = aIdx1 >> 4, ac1 = aIdx1 & 15;
    float4 ra0, ra1, rb[4];
    ra0 = *(const float4*)(A + (size_t)r0 * lda + kbase + ac0 * 4);
    ra1 = *(const float4*)(A + (size_t)r1 * lda + kbase + ac1 * 4);
    #pragma unroll
    for (int e = 0; e < 4; e++) {
        int idx = ttid + 256 * e;
        int bk = idx >> 4, c4 = idx & 15;
        rb[e] = *(const float4*)(Bw + (size_t)(kbase + bk) * ldb + c4 * 4);
    }

    for (int ch = 0; ch < nch; ch++) {
        // stage A duplicated f32x2, B raw
        {
            float2* pa = (float2*)sA2;
            pa[(ac0 * 4 + 0) * 33 + r0] = make_float2(ra0.x, ra0.x);
            pa[(ac0 * 4 + 1) * 33 + r0] = make_float2(ra0.y, ra0.y);
            pa[(ac0 * 4 + 2) * 33 + r0] = make_float2(ra0.z, ra0.z);
            pa[(ac0 * 4 + 3) * 33 + r0] = make_float2(ra0.w, ra0.w);
            pa[(ac1 * 4 + 0) * 33 + r1] = make_float2(ra1.x, ra1.x);
            pa[(ac1 * 4 + 1) * 33 + r1] = make_float2(ra1.y, ra1.y);
            pa[(ac1 * 4 + 2) * 33 + r1] = make_float2(ra1.z, ra1.z);
            pa[(ac1 * 4 + 3) * 33 + r1] = make_float2(ra1.w, ra1.w);
            #pragma unroll
            for (int e = 0; e < 4; e++) {
                int idx = ttid + 256 * e;
                int bk = idx >> 4, c4 = idx & 15;
                *(float4*)(sB + bk * 64 + c4 * 4) = rb[e];
            }
        }
        __syncthreads();
        if (ch + 1 < nch) {
            int kn = kbase + (ch + 1) * 64;
            ra0 = *(const float4*)(A + (size_t)r0 * lda + kn + ac0 * 4);
            ra1 = *(const float4*)(A + (size_t)r1 * lda + kn + ac1 * 4);
            #pragma unroll
            for (int e = 0; e < 4; e++) {
                int idx = ttid + 256 * e;
                int bk = idx >> 4, c4 = idx & 15;
                rb[e] = *(const float4*)(Bw + (size_t)(kn + bk) * ldb + c4 * 4);
            }
        }
        #pragma unroll
        for (int kk = 0; kk < 64; kk++) {
            unsigned long long a2 = *(const unsigned long long*)(sA2 + (kk * 33 + lane) * 2);
            ulonglong2 b01 = *(const ulonglong2*)(sB + kk * 64 + tw * 8);
            ulonglong2 b23 = *(const ulonglong2*)(sB + kk * 64 + tw * 8 + 4);
            fma2(acc0, a2, b01.x);
            fma2(acc1, a2, b01.y);
            fma2(acc2, a2, b23.x);
            fma2(acc3, a2, b23.y);
        }
        __syncthreads();
    }

    // cross-team accumulator combine: team1 -> smem (its sB region), team0 finalizes
    float o[8];
    unpack2(acc0, o[0], o[1]); unpack2(acc1, o[2], o[3]);
    unpack2(acc2, o[4], o[5]); unpack2(acc3, o[6], o[7]);
    float* xb = (float*)(dsm + TEAM_BYTES + 16896);
    if (team == 1) {
        *(float4*)(xb + ttid * 8)     = make_float4(o[0], o[1], o[2], o[3]);
        *(float4*)(xb + ttid * 8 + 4) = make_float4(o[4], o[5], o[6], o[7]);
    }
    __syncthreads();
    if (team == 0) {
        #pragma unroll
        for (int j = 0; j < 8; j++) o[j] += xb[ttid * 8 + j];
        if (bias) {
            #pragma unroll
            for (int j = 0; j < 8; j++) o[j] += bias[tw * 8 + j];
        }
        if (act) {
            #pragma unroll
            for (int j = 0; j < 8; j++) o[j] = geluf(o[j]);
        }
        *(float4*)(C + (size_t)lane * ldc + tw * 8)     = make_float4(o[0], o[1], o[2], o[3]);
        *(float4*)(C + (size_t)lane * ldc + tw * 8 + 4) = make_float4(o[4], o[5], o[6], o[7]);
    }
    __syncthreads();
}

// ---------------- the persistent mega kernel ----------------
__global__ void __launch_bounds__(NT, 1)
mega(const float* __restrict__ sequence, const float* __restrict__ input_mask,
     const float* __restrict__ w_init, const float* __restrict__ b_init,
     const float* __restrict__ ln1_g, const float* __restrict__ ln1_b,
     const float* __restrict__ scorer_w, const float* __restrict__ scorer_b,
     const float* __restrict__ conv_w, const float* __restrict__ conv_b,
     const float* __restrict__ start,
     const float* __restrict__ wcell1_w, const float* __restrict__ wcell1_b,
     const float* __restrict__ wcell2_w, const float* __restrict__ wcell2_b,
     const float* __restrict__ ln2_g, const float* __restrict__ ln2_b,
     float* __restrict__ out) {
    extern __shared__ char dsm[];
    __shared__ float sred[16];
    __shared__ float sscore[8];
    __shared__ int   ssel[BEAMW];

    int tid = threadIdx.x;
    int bid = blockIdx.x;
    int h   = tid >> 8;        // half-block id
    int col = tid & 255;       // column within half

    // ---- init 1: seq = LN1(sequence @ w_init + b_init); one row per half ----
    {
        float* sX = (float*)dsm;   // [2][256]
        for (int job = bid; job < (NB * SL) / 2; job += G) {
            int row = job * 2 + h;
            sX[h * 256 + col] = sequence[(size_t)row * DIM + col];
            __syncthreads();
            float acc = 0.f;
            for (int i = 0; i < DIM; i++)
                acc += sX[h * 256 + i] * w_init[i * DIM + col];
            float y = acc + b_init[col];
            float s1 = halfReduceSum(y, sred);
            float s2 = halfReduceSum(y * y, sred);
            float m = s1 * (1.0f / DIM);
            float var = s2 * (1.0f / DIM) - m * m;
            d_seq[(size_t)row * DIM + col] = (y - m) * rsqrtf(var + LNEPS) * ln1_g[col] + ln1_b[col];
            __syncthreads();
        }
    }
    gbar();

    // ---- init 2: stack init + first gather (K=1) ----
    if (bid < NB) {
        int n = bid;
        float* stk0 = d_stk[0] + (size_t)(n * BEAMW) * SL * DIM;
        if (h == 0) {
            stk0[col]       = d_seq[(size_t)(n * SL + 0) * DIM + col];
            stk0[DIM + col] = d_seq[(size_t)(n * SL + 1) * DIM + col];
            if (col == 0) {
                d_p[0][n * BEAMW] = (input_mask[n * SL + 1] > 0.5f) ? 1 : 0;
                d_q[0][n * BEAMW] = 0;
            }
        }
        __syncthreads();
        if (h == 0) {
            int p = d_p[0][n * BEAMW];
            float c1 = (p >= 1) ? stk0[(p - 1) * DIM + col] : start[col];
            float c2 = stk0[p * DIM + col];
            float cu = d_seq[(size_t)(n * SL + 2) * DIM + col];
            d_win[n * 768 + col]       = c1;
            d_win[n * 768 + 256 + col] = c2;
            d_win[n * 768 + 512 + col] = cu;
            d_cc[n * 512 + col]        = c1;
            d_cc[n * 512 + 256 + col]  = c2;
        }
    }
    gbar();

    int K = 1, buf = 0;
    for (int t = 2; t <= 2 * SL - 2; t++) {
        int M  = NB * K;
        int rt = M / 32;
        int newK = (2 * K < BEAMW) ? 2 * K : BEAMW;

        // ---- phase B: cell1 (fused gelu) + conv partials (ks2) ----
        int c1Jobs = rt * 16;
        int cvJobs = rt * 4 * 2;
        for (int job = bid; job < c1Jobs + cvJobs; job += G) {
            if (job < c1Jobs) {
                int ri = job >> 4, ct = job & 15;
                gemm_tile(d_cc + (size_t)ri * 32 * 512, 512,
                          wcell1_w + ct * 64, 1024,
                          0, 4,
                          d_inter + (size_t)ri * 32 * 1024 + ct * 64, 1024,
                          wcell1_b + ct * 64, 1, dsm);
            } else {
                int j = job - c1Jobs;
                int ks = j & 1, ct = (j >> 1) & 3, ri = j >> 3;
                gemm_tile(d_win + (size_t)ri * 32 * 768, 768,
                          conv_w + ct * 64, 256,
                          ks * 384, 3,
                          d_cpart + (size_t)ks * 32768 + (size_t)ri * 32 * 256 + ct * 64, 256,
                          nullptr, 0, dsm);
            }
        }
        gbar();

        // ---- phase C: cell2 partials (ks2) ----
        for (int job = bid; job < rt * 32; job += G) {
            int ks = job & 1, ct = (job >> 1) & 15, ri = job >> 5;
            gemm_tile(d_inter + (size_t)ri * 32 * 1024 + ks * 512, 1024,
                      wcell2_w + (size_t)ks * 512 * 1024 + ct * 64, 1024,
                      0, 4,
                      d_c2 + (size_t)ks * 131072 + (size_t)ri * 32 * 1024 + ct * 64, 1024,
                      nullptr, 0, dsm);
        }
        gbar();

        // ---- phase EF: score finalize + compose + top-k + beam copy + next gather ----
        if (bid < NB) {
            int n = bid;
            float* red = (float*)dsm;    // [BEAMW][256], overlays team0 sA2

            // 1. scores (two beams at a time, one per half)
            for (int k0 = 0; k0 < K; k0 += 2) {
                int k = k0 + h;
                int valid = (k < K);
                int kk2 = valid ? k : 0;
                int m = n * K + kk2;
                float s = d_cpart[m * 256 + col] + d_cpart[32768 + m * 256 + col];
                float y = valid ? geluf(s + conv_b[col]) * scorer_w[col] : 0.f;
                float dot = halfReduceSum(y, sred);
                if (col == 0 && valid) {
                    float dec = sigmoidf_(dot + scorer_b[0]);
                    int p = d_p[buf][n * BEAMW + k];
                    int q = d_q[buf][n * BEAMW + k];
                    float lp  = (p >= 1) ? 1.0f : 0.0f;
                    float cmf = (q < SL - 2) ? input_mask[n * SL + 2 + q] : 0.0f;
                    float bz  = ((lp == 0.0f) && (cmf == 0.0f)) ? 1.0f : 0.0f;
                    float rs = cmf * dec + (1.0f - cmf);
                    rs = lp * rs;
                    rs = bz + (1.0f - bz) * rs;
                    rs = logf(rs + EPSC);
                    float ss = lp * (1.0f - dec) + (1.0f - lp);
                    ss = cmf * ss;
                    ss = (1.0f - bz) * ss;
                    ss = logf(ss + EPSC);
                    sscore[k] = rs;
                    sscore[4 + k] = ss;
                }
            }
            // 2. compose (sum cell2 partials + bias -> gates + LN2)
            for (int k0 = 0; k0 < K; k0 += 2) {
                int k = k0 + h;
                int valid = (k < K);
                int kk2 = valid ? k : 0;
                int m = n * K + kk2;
                const float* c20 = d_c2 + (size_t)m * 1024;
                const float* c21 = d_c2 + 131072 + (size_t)m * 1024;
                float v0 = c20[col]       + c21[col]       + wcell2_b[col];
                float v1 = c20[256 + col] + c21[256 + col] + wcell2_b[256 + col];
                float v2 = c20[512 + col] + c21[512 + col] + wcell2_b[512 + col];
                float v3 = c20[768 + col] + c21[768 + col] + wcell2_b[768 + col];
                float x = sigmoidf_(v0) * d_cc[m * 512 + col]
                        + sigmoidf_(v1) * d_cc[m * 512 + 256 + col]
                        + sigmoidf_(v2) * v3;
                float xm = valid ? x : 0.f;
                float s1 = halfReduceSum(xm, sred);
                float s2 = halfReduceSum(xm * xm, sred);
                if (valid) {
                    float mn = s1 * (1.0f / DIM);
                    float var = s2 * (1.0f / DIM) - mn * mn;
                    red[k * 256 + col] = (x - mn) * rsqrtf(var + LNEPS) * ln2_g[col] + ln2_b[col];
                }
            }
            __syncthreads();
            // 3. stable top-k
            if (tid == 0) {
                int C = 2 * K;
                float sc[8];
                for (int c = 0; c < C; c++)
                    sc[c] = (c < K) ? sscore[c] : sscore[4 + (c - K)];
                if (C <= BEAMW) {
                    for (int s = 0; s < C; s++) { ssel[s] = s; d_bscore[n * BEAMW + s] = sc[s]; }
                } else {
                    bool used[8];
                    for (int c = 0; c < C; c++) used[c] = false;
                    for (int s = 0; s < BEAMW; s++) {
                        int best = -1; float bv = 0.f;
                        for (int c = 0; c < C; c++) {
                            if (used[c]) continue;
                            if (best < 0 || sc[c] > bv) { best = c; bv = sc[c]; }
                        }
                        used[best] = true;
                        ssel[s] = best;
                        d_bscore[n * BEAMW + s] = bv;
                    }
                }
            }
            __syncthreads();
            // 4. beam copy (one beam per half)
            int nb2 = buf ^ 1;
            for (int s = h; s < newK; s += 2) {
                int c = ssel[s];
                int isred = (c < K);
                int k = isred ? c : (c - K);
                int p = d_p[buf][n * BEAMW + k];
                int q = d_q[buf][n * BEAMW + k];
                int lp = (p >= 1);
                float cmf = (q < SL - 2) ? input_mask[n * SL + 2 + q] : 0.0f;
                int cm = (cmf > 0.5f);
                int wr_pos = -1, newp = p, newq = q;
                const float* wr_g = nullptr;
                int wr_sm = 0;
                if (isred) {
                    if (lp) { wr_pos = p - 1; newp = p - 1; wr_sm = 1; }
                } else {
                    newq = q + 1;
                    if (cm) { wr_pos = p + 1; newp = p + 1; wr_g = &d_seq[(size_t)(n * SL + 2 + q) * DIM]; }
                }
                const float* src = d_stk[buf] + (size_t)(n * BEAMW + k) * SL * DIM;
                float* dst       = d_stk[nb2] + (size_t)(n * BEAMW + s) * SL * DIM;
                int len = (newp + 1) * DIM;
                for (int idx = col; idx < len; idx += 256) {
                    int pos = idx >> 8;
                    float v = (pos == wr_pos) ? (wr_sm ? red[k * 256 + (idx & 255)]
                                                       : wr_g[idx & 255])
                                              : src[idx];
                    dst[idx] = v;
                }
                if (col == 0) {
                    d_p[nb2][n * BEAMW + s] = newp;
                    d_q[nb2][n * BEAMW + s] = newq;
                }
            }
            __syncthreads();
            // 5. gather for next iteration
            for (int s = h; s < newK; s += 2) {
                int m2 = n * newK + s;
                int p = d_p[nb2][n * BEAMW + s];
                int q = d_q[nb2][n * BEAMW + s];
                const float* stk = d_stk[nb2] + (size_t)(n * BEAMW + s) * SL * DIM;
                float c1 = (p >= 1) ? stk[(p - 1) * DIM + col] : start[col];
                float c2 = stk[p * DIM + col];
                float cu = (q < SL - 2) ? d_seq[(size_t)(n * SL + 2 + q) * DIM + col] : 0.f;
                d_win[m2 * 768 + col]       = c1;
                d_win[m2 * 768 + 256 + col] = c2;
                d_win[m2 * 768 + 512 + col] = cu;
                d_cc[m2 * 512 + col]        = c1;
                d_cc[m2 * 512 + 256 + col]  = c2;
            }
        }
        gbar();
        buf ^= 1;
        K = newK;
    }

    // ---- final: softmax over beam scores, weighted top-of-stack sum ----
    if (bid < NB && h == 0) {
        int n = bid;
        float sc[BEAMW];
        float mx = -1e30f;
        #pragma unroll
        for (int k = 0; k < BEAMW; k++) {
            sc[k] = d_bscore[n * BEAMW + k];
            mx = fmaxf(mx, sc[k]);
        }
        float e[BEAMW], sum = 0.f;
        #pragma unroll
        for (int k = 0; k < BEAMW; k++) { e[k] = expf(sc[k] - mx); sum += e[k]; }
        float o = 0.f;
        #pragma unroll
        for (int k = 0; k < BEAMW; k++) {
            int p = d_p[buf][n * BEAMW + k];
            o += (e[k] / sum) * d_stk[buf][((size_t)(n * BEAMW + k) * SL + p) * DIM + col];
        }
        out[(size_t)n * DIM + col] = o;
    }
}

// ---------------- host launcher ----------------
extern "C" void kernel_launch(void* const* d_in, const int* in_sizes, int n_in,
                              void* d_out, int out_size) {
    const float* sequence   = (const float*)d_in[0];
    const float* input_mask = (const float*)d_in[1];
    const float* w_init     = (const float*)d_in[2];
    const float* b_init     = (const float*)d_in[3];
    const float* ln1_g      = (const float*)d_in[4];
    const float* ln1_b      = (const float*)d_in[5];
    const float* scorer_w   = (const float*)d_in[6];
    const float* scorer_b   = (const float*)d_in[7];
    const float* conv_w     = (const float*)d_in[8];
    const float* conv_b     = (const float*)d_in[9];
    const float* start      = (const float*)d_in[10];
    const float* wcell1_w   = (const float*)d_in[11];
    const float* wcell1_b   = (const float*)d_in[12];
    const float* wcell2_w   = (const float*)d_in[13];
    const float* wcell2_b   = (const float*)d_in[14];
    const float* ln2_g      = (const float*)d_in[15];
    const float* ln2_b      = (const float*)d_in[16];
    float* out = (float*)d_out;

    cudaFuncSetAttribute(mega, cudaFuncAttributeMaxDynamicSharedMemorySize, SMEM_DYN);
    mega<<<G, NT, SMEM_DYN>>>(sequence, input_mask, w_init, b_init, ln1_g, ln1_b,
                              scorer_w, scorer_b, conv_w, conv_b, start,
                              wcell1_w, wcell1_b, wcell2_w, wcell2_b, ln2_g, ln2_b, out);
}